// round 12
// baseline (speedup 1.0000x reference)
#include <cuda_runtime.h>
#include <cuda_bf16.h>
#include <cstdint>

#define NU   128
#define MS   64
#define INC  323          // [0:128) interact | [128:192) corr | [192:320) topic | 320 t | 321 a | 322 h
#define BMAX 4096
#define TB   32

// ---------------- scratch (device globals; no allocation) ----------------
__device__ float g_hpt   [BMAX*NU];
__device__ float g_lg    [BMAX*NU];
__device__ float g_c     [BMAX*NU];
__device__ float g_preds [BMAX];
__device__ float g_htilde[BMAX*NU];
__device__ float g_ws    [3*NU];
__device__ float g_gain  [3*BMAX*NU];
__device__ float g_fdot  [4ULL*BMAX*NU];
__device__ __nv_bfloat16 g_w1hi[NU*NU];
__device__ __nv_bfloat16 g_w1lo[NU*NU];

__device__ __forceinline__ float sigmoidf(float x){ return 1.f/(1.f+__expf(-x)); }
__device__ __forceinline__ int swzA(int row, int cb){ return row*256 + (cb ^ ((row&7)<<4)); }
__device__ __forceinline__ uint32_t bfu(__nv_bfloat16 h){ return (uint32_t)__bfloat16_as_ushort(h); }

#define MMA16816(c, a, b0v, b1v) \
    asm volatile("mma.sync.aligned.m16n8k16.row.col.f32.bf16.bf16.f32 " \
        "{%0,%1,%2,%3}, {%4,%5,%6,%7}, {%8,%9}, {%0,%1,%2,%3};" \
        : "+f"((c)[0]), "+f"((c)[1]), "+f"((c)[2]), "+f"((c)[3]) \
        : "r"((a)[0]), "r"((a)[1]), "r"((a)[2]), "r"((a)[3]), "r"(b0v), "r"(b1v))

// ---------------- K0: colsums of gate3_W factor rows ----------------
__global__ void k0_wsum(const float* __restrict__ g3W){
    int n = threadIdx.x;
    #pragma unroll
    for(int g=0; g<3; g++){
        float s = 0.f;
        for(int u=0; u<50; u++) s += g3W[(256 + g*50 + u)*NU + n];
        g_ws[g*NU + n] = s;
    }
}

// ---------------- K0b: split-transpose gate3_W[0:128] -> bf16 hi/lo, swizzled ----------------
__global__ __launch_bounds__(256) void k0b_wsplit(const float* __restrict__ g3W){
    int id = blockIdx.x*256 + threadIdx.x;
    int n = id >> 7, k = id & 127;
    float v = g3W[k*NU + n];
    __nv_bfloat16 hi = __float2bfloat16(v);
    __nv_bfloat16 lo = __float2bfloat16(v - __bfloat162float(hi));
    int off = swzA(n, 2*k);
    *(__nv_bfloat16*)((char*)g_w1hi + off) = hi;
    *(__nv_bfloat16*)((char*)g_w1lo + off) = lo;
}

// ---------------- K1: h_pre_tilde ----------------
__global__ __launch_bounds__(128) void k1_hpt(const float* __restrict__ inp,
                                              const float* __restrict__ states){
    int b = blockIdx.x, n = threadIdx.x;
    __shared__ float corr[MS];
    if(n < MS) corr[n] = inp[(size_t)b*INC + NU + n];
    __syncthreads();
    const float* hp = states + (size_t)b*MS*NU;
    float a0=0.f,a1=0.f,a2=0.f,a3=0.f;
    #pragma unroll
    for(int m=0; m<MS; m+=4){
        a0 = fmaf(corr[m+0], hp[(m+0)*NU + n], a0);
        a1 = fmaf(corr[m+1], hp[(m+1)*NU + n], a1);
        a2 = fmaf(corr[m+2], hp[(m+2)*NU + n], a2);
        a3 = fmaf(corr[m+3], hp[(m+3)*NU + n], a3);
    }
    g_hpt[b*NU + n] = (a0+a1)+(a2+a3);
}

// ================= register-tiled GEMM core (with W prefetch) =================
__device__ __forceinline__ void gemm_rt(const float (*A)[NU], const float* __restrict__ W,
                                        float (*Ws)[NU], int rg, int cg, float acc[4][4]){
    int t = threadIdx.x;
    float4 pre[4];
    {
        const float4* src = (const float4*)W;
        #pragma unroll
        for(int i=0;i<4;i++) pre[i] = src[t + i*256];
    }
    #pragma unroll 1
    for(int kt=0; kt<4; kt++){
        __syncthreads();
        {
            float4* dst = (float4*)Ws;
            #pragma unroll
            for(int i=0;i<4;i++) dst[t + i*256] = pre[i];
        }
        __syncthreads();
        if(kt < 3){
            const float4* src = (const float4*)(W + (kt+1)*32*NU);
            #pragma unroll
            for(int i=0;i<4;i++) pre[i] = src[t + i*256];
        }
        #pragma unroll
        for(int k=0; k<32; k+=4){
            float4 w0 = *(const float4*)&Ws[k+0][cg*4];
            float4 w1 = *(const float4*)&Ws[k+1][cg*4];
            float4 w2 = *(const float4*)&Ws[k+2][cg*4];
            float4 w3 = *(const float4*)&Ws[k+3][cg*4];
            #pragma unroll
            for(int i=0;i<4;i++){
                float4 a = *(const float4*)&A[rg*4+i][kt*32+k];
                acc[i][0]=fmaf(a.x,w0.x,fmaf(a.y,w1.x,fmaf(a.z,w2.x,fmaf(a.w,w3.x,acc[i][0]))));
                acc[i][1]=fmaf(a.x,w0.y,fmaf(a.y,w1.y,fmaf(a.z,w2.y,fmaf(a.w,w3.y,acc[i][1]))));
                acc[i][2]=fmaf(a.x,w0.z,fmaf(a.y,w1.z,fmaf(a.z,w2.z,fmaf(a.w,w3.z,acc[i][2]))));
                acc[i][3]=fmaf(a.x,w0.w,fmaf(a.y,w1.w,fmaf(a.z,w2.w,fmaf(a.w,w3.w,acc[i][3]))));
            }
        }
    }
}

// ---------------- K2a: slot 0=preds, 1..3=gates, 4=c ----------------
struct SM2A {
    float A0[TB][NU];
    float A1[TB][NU];
    float Ws[32][NU];
    float fact[TB][4];
};

__global__ __launch_bounds__(256) void k2a(const float* __restrict__ inp,
    const float* __restrict__ outW, const float* __restrict__ outb,
    const float* __restrict__ tgW,  const float* __restrict__ tgb,
    const float* __restrict__ agW,  const float* __restrict__ agb,
    const float* __restrict__ hgW,  const float* __restrict__ hgb,
    const float* __restrict__ g3W,  const float* __restrict__ g3b){

    extern __shared__ char smraw[];
    SM2A& S = *(SM2A*)smraw;
    int t = threadIdx.x, rg = t>>5, cg = t&31;
    int b0 = blockIdx.x*TB;
    int slot = blockIdx.y;

    for(int i=t; i<TB*NU; i+=256){
        int r = i>>7, c = i&127;
        S.A0[r][c] = g_hpt[(b0+r)*NU + c];
        S.A1[r][c] = (slot==0) ? inp[(size_t)(b0+r)*INC + NU + MS + c]
                               : inp[(size_t)(b0+r)*INC + c];
    }
    for(int i=t; i<TB*3; i+=256){ int r=i/3, g=i%3; S.fact[r][g] = inp[(size_t)(b0+r)*INC + 320 + g]; }

    float acc[4][4];
    #pragma unroll
    for(int i=0;i<4;i++){ acc[i][0]=acc[i][1]=acc[i][2]=acc[i][3]=0.f; }

    if(slot == 0){
        gemm_rt(S.A0, outW,         S.Ws, rg, cg, acc);
        gemm_rt(S.A1, outW + NU*NU, S.Ws, rg, cg, acc);
        float s[4];
        #pragma unroll
        for(int i=0;i<4;i++){
            s[i]=0.f;
            #pragma unroll
            for(int j=0;j<4;j++) s[i] += sigmoidf(acc[i][j] + outb[cg*4+j]);
        }
        #pragma unroll
        for(int off=16; off; off>>=1){
            #pragma unroll
            for(int i=0;i<4;i++) s[i] += __shfl_xor_sync(0xffffffffu, s[i], off);
        }
        if(cg==0){
            #pragma unroll
            for(int i=0;i<4;i++) g_preds[b0 + rg*4 + i] = s[i] * (1.f/NU);
        }
    } else if(slot <= 3){
        int g = slot - 1;
        const float* Wg = (g==0)? tgW : (g==1)? agW : hgW;
        const float* bg = (g==0)? tgb : (g==1)? agb : hgb;
        gemm_rt(S.A0, Wg,         S.Ws, rg, cg, acc);
        gemm_rt(S.A1, Wg + NU*NU, S.Ws, rg, cg, acc);
        #pragma unroll
        for(int i=0;i<4;i++){
            int b = b0 + rg*4 + i;
            float f = S.fact[rg*4+i][g];
            float gain = 0.3f + 0.7f*sigmoidf(10.f*(f - 0.3f));
            float4 o;
            o.x = sigmoidf((acc[i][0] + bg[cg*4+0]) * gain);
            o.y = sigmoidf((acc[i][1] + bg[cg*4+1]) * gain);
            o.z = sigmoidf((acc[i][2] + bg[cg*4+2]) * gain);
            o.w = sigmoidf((acc[i][3] + bg[cg*4+3]) * gain);
            *(float4*)&g_gain[(size_t)g*BMAX*NU + b*NU + cg*4] = o;
        }
    } else {
        gemm_rt(S.A1, g3W + NU*NU, S.Ws, rg, cg, acc);
        #pragma unroll
        for(int i=0;i<4;i++){
            int b = b0 + rg*4 + i;
            float f0=S.fact[rg*4+i][0], f1=S.fact[rg*4+i][1], f2=S.fact[rg*4+i][2];
            #pragma unroll
            for(int j=0;j<4;j++){
                int n = cg*4 + j;
                g_c[b*NU + n] = acc[i][j] + f0*g_ws[n] + f1*g_ws[NU+n] + f2*g_ws[2*NU+n] + g3b[n];
            }
        }
    }
}

// ---------------- K2b v2: slot = r; computes Wf[r] * prod_g(dot_g + pad_g) ----------------
struct SM2B {
    float A[3][TB][NU];
    float Ws[32][NU];
};

__global__ __launch_bounds__(256) void k2b(const float* __restrict__ tw,
    const float* __restrict__ aw, const float* __restrict__ hw,
    const float* __restrict__ Wf){
    extern __shared__ char smraw[];
    SM2B& S = *(SM2B*)smraw;
    int t = threadIdx.x, rg = t>>5, cg = t&31;
    int b0 = blockIdx.x*TB;
    int r = blockIdx.y;

    for(int i=t; i<3*TB*NU; i+=256){
        int g = i/(TB*NU), rr = (i>>7)&(TB-1), c = i&127;
        S.A[g][rr][c] = g_gain[(size_t)g*BMAX*NU + (b0+rr)*NU + c];
    }

    const float* Wg[3] = {tw, aw, hw};
    float acc3[3][4][4];
    #pragma unroll 1
    for(int g=0; g<3; g++){
        #pragma unroll
        for(int i=0;i<4;i++){ acc3[g][i][0]=acc3[g][i][1]=acc3[g][i][2]=acc3[g][i][3]=0.f; }
        gemm_rt(S.A[g], Wg[g] + (size_t)r*129*NU, S.Ws, rg, cg, acc3[g]);
        const float* pad = Wg[g] + ((size_t)r*129 + 128)*NU;
        #pragma unroll
        for(int i=0;i<4;i++)
            #pragma unroll
            for(int j=0;j<4;j++)
                acc3[g][i][j] += pad[cg*4+j];
    }
    float wf = __ldg(Wf + r);
    float* dst = g_fdot + (size_t)r*BMAX*NU;
    #pragma unroll
    for(int i=0;i<4;i++){
        int b = b0 + rg*4 + i;
        float4 o;
        o.x = wf * acc3[0][i][0]*acc3[1][i][0]*acc3[2][i][0];
        o.y = wf * acc3[0][i][1]*acc3[1][i][1]*acc3[2][i][1];
        o.z = wf * acc3[0][i][2]*acc3[1][i][2]*acc3[2][i][2];
        o.w = wf * acc3[0][i][3]*acc3[1][i][3]*acc3[2][i][3];
        *(float4*)&dst[b*NU + cg*4] = o;
    }
}

// ---------------- K3c: combine -> learning_gain ----------------
__global__ __launch_bounds__(256) void k3c(const float* __restrict__ bias, int B){
    int idx = blockIdx.x*256 + threadIdx.x;
    size_t e = (size_t)idx*4;
    if(e >= (size_t)B*NU) return;
    int n = (int)(e & 127);
    float4 bs = *(const float4*)&bias[n];
    float4 acc = bs;
    #pragma unroll
    for(int r=0; r<4; r++){
        float4 p = *(const float4*)&g_fdot[(size_t)r*BMAX*NU + e];
        acc.x += p.x; acc.y += p.y; acc.z += p.z; acc.w += p.w;
    }
    float4 o;
    o.x = fmaxf(acc.x, 0.f);
    o.y = fmaxf(acc.y, 0.f);
    o.z = fmaxf(acc.z, 0.f);
    o.w = fmaxf(acc.w, 0.f);
    *(float4*)&g_lg[e] = o;
}

// ---------------- K4 v3: warp tile M=32 x N=64 (B smem traffic halved) ----------------
#define SM4_WHI 0
#define SM4_WLO 32768
#define SM4_HTW 65536                     // 8 warps * 64 floats = 2 KB
#define SM4_AUX (65536 + 2048)
#define SM4_TOTAL (SM4_AUX + 2560)

__global__ __launch_bounds__(256, 2)
void k4_main(const float* __restrict__ inp, const float* __restrict__ states,
             float* __restrict__ out, int B){
    extern __shared__ char sm[];
    float* htw    = (float*)(sm + SM4_HTW);          // [8][64]
    float* corr_s = (float*)(sm + SM4_AUX);          // 128
    float* c_s    = (float*)(sm + SM4_AUX + 512);    // 256
    float* lg_s   = (float*)(sm + SM4_AUX + 1536);   // 256

    int t = threadIdx.x, w = t>>5, l = t&31;
    int g = l>>2, tt = l&3;
    int mg = w & 3, ng = w >> 2;          // warp tile: rows [mg*32,+32), cols [ng*64,+64)
    int bb = blockIdx.x;
    size_t row0 = (size_t)bb*128;

    // stage W hi/lo
    {
        const uint4* shv = (const uint4*)g_w1hi;
        const uint4* slv = (const uint4*)g_w1lo;
        uint4* dh = (uint4*)(sm + SM4_WHI);
        uint4* dl = (uint4*)(sm + SM4_WLO);
        for(int i=t; i<2048; i+=256){ dh[i]=shv[i]; dl[i]=slv[i]; }
    }
    if(t < 128) corr_s[t] = inp[(size_t)(2*bb + (t>>6))*INC + NU + (t&63)];
    c_s[t]  = g_c [(size_t)2*bb*NU + t];
    lg_s[t] = g_lg[(size_t)2*bb*NU + t];

    // A row pointers: mt in {0,1}: rows mg*32 + mt*16 + g and +8
    const float* arow[2][2];
    #pragma unroll
    for(int mt=0; mt<2; mt++){
        arow[mt][0] = states + (row0 + mg*32 + mt*16 + g    )*NU;
        arow[mt][1] = states + (row0 + mg*32 + mt*16 + g + 8)*NU;
    }

    float acc[2][8][4];
    #pragma unroll
    for(int mt=0; mt<2; mt++)
        #pragma unroll
        for(int nt=0; nt<8; nt++){ acc[mt][nt][0]=acc[mt][nt][1]=acc[mt][nt][2]=acc[mt][nt][3]=0.f; }

    __syncthreads();

    // mainloop, double-buffered A
    float2 av0[2][4], av1[2][4];
    {
        int c0 = tt*2;
        #pragma unroll
        for(int mt=0; mt<2; mt++){
            av0[mt][0] = *(const float2*)(arow[mt][0] + c0);
            av0[mt][1] = *(const float2*)(arow[mt][1] + c0);
            av0[mt][2] = *(const float2*)(arow[mt][0] + c0 + 8);
            av0[mt][3] = *(const float2*)(arow[mt][1] + c0 + 8);
        }
    }
    #pragma unroll
    for(int kt=0; kt<8; kt++){
        if(kt < 7){
            int c0 = (kt+1)*16 + tt*2;
            #pragma unroll
            for(int mt=0; mt<2; mt++){
                av1[mt][0] = *(const float2*)(arow[mt][0] + c0);
                av1[mt][1] = *(const float2*)(arow[mt][1] + c0);
                av1[mt][2] = *(const float2*)(arow[mt][0] + c0 + 8);
                av1[mt][3] = *(const float2*)(arow[mt][1] + c0 + 8);
            }
        }
        uint32_t ah[2][4], al[2][4];
        #pragma unroll
        for(int mt=0; mt<2; mt++)
            #pragma unroll
            for(int i=0;i<4;i++){
                float x = av0[mt][i].x, y = av0[mt][i].y;
                __nv_bfloat16 hx = __float2bfloat16(x), hy = __float2bfloat16(y);
                ah[mt][i] = bfu(hx) | (bfu(hy)<<16);
                al[mt][i] = bfu(__float2bfloat16(x - __bfloat162float(hx)))
                          | (bfu(__float2bfloat16(y - __bfloat162float(hy)))<<16);
            }
        int cb0 = kt*32 + tt*4, cb1 = cb0 + 16;
        #pragma unroll
        for(int nt=0; nt<8; nt++){
            int brow = ng*64 + nt*8 + g;
            uint32_t bh0 = *(const uint32_t*)(sm + SM4_WHI + swzA(brow, cb0));
            uint32_t bh1 = *(const uint32_t*)(sm + SM4_WHI + swzA(brow, cb1));
            uint32_t bl0 = *(const uint32_t*)(sm + SM4_WLO + swzA(brow, cb0));
            uint32_t bl1 = *(const uint32_t*)(sm + SM4_WLO + swzA(brow, cb1));
            #pragma unroll
            for(int mt=0; mt<2; mt++){
                MMA16816(acc[mt][nt], ah[mt], bh0, bh1);
                MMA16816(acc[mt][nt], al[mt], bh0, bh1);
                MMA16816(acc[mt][nt], ah[mt], bl0, bl1);
            }
        }
        #pragma unroll
        for(int mt=0; mt<2; mt++)
            #pragma unroll
            for(int i=0;i<4;i++) av0[mt][i] = av1[mt][i];
    }

    // epilogue
    int batch = mg >> 1;                  // rows mg*32.. belong to batch (mg>=2 -> 1)
    int boff = batch * NU;
    float* hbase = out + (size_t)2*B + row0*NU;

    #pragma unroll
    for(int nt=0; nt<8; nt++){
        int n0 = ng*64 + nt*8 + tt*2;
        float2 cc = *(const float2*)(c_s  + boff + n0);
        float2 ll = *(const float2*)(lg_s + boff + n0);
        float px = 0.f, py = 0.f;
        #pragma unroll
        for(int mt=0; mt<2; mt++){
            int m0 = mg*32 + mt*16 + g, m1 = m0 + 8;
            float cr0 = corr_s[m0], cr1 = corr_s[m1];
            float2 a0v = *(const float2*)(arow[mt][0] + n0);
            float2 a1v = *(const float2*)(arow[mt][1] + n0);
            float2 o0, o1;
            o0.x = a0v.x * sigmoidf(acc[mt][nt][0] + cc.x) + cr0*ll.x;
            o0.y = a0v.y * sigmoidf(acc[mt][nt][1] + cc.y) + cr0*ll.y;
            o1.x = a1v.x * sigmoidf(acc[mt][nt][2] + cc.x) + cr1*ll.x;
            o1.y = a1v.y * sigmoidf(acc[mt][nt][3] + cc.y) + cr1*ll.y;
            *(float2*)(hbase + (size_t)m0*NU + n0) = o0;
            *(float2*)(hbase + (size_t)m1*NU + n0) = o1;
            px += fmaf(cr0, o0.x, cr1*o1.x);
            py += fmaf(cr0, o0.y, cr1*o1.y);
        }
        px += __shfl_xor_sync(0xffffffffu, px, 4);
        py += __shfl_xor_sync(0xffffffffu, py, 4);
        px += __shfl_xor_sync(0xffffffffu, px, 8);
        py += __shfl_xor_sync(0xffffffffu, py, 8);
        px += __shfl_xor_sync(0xffffffffu, px, 16);
        py += __shfl_xor_sync(0xffffffffu, py, 16);
        if(g == 0){ htw[w*64 + nt*8 + tt*2] = px; htw[w*64 + nt*8 + tt*2 + 1] = py; }
    }
    __syncthreads();
    {
        int batch2 = t>>7, col = t&127;
        int ngc = col>>6, lc = col&63;
        float s = htw[(ngc*4 + batch2*2 + 0)*64 + lc]
                + htw[(ngc*4 + batch2*2 + 1)*64 + lc];
        g_htilde[(size_t)(2*bb + batch2)*NU + col] = s;
    }
}

// ---------------- K5: after_preds from g_htilde + result ----------------
struct SM5 {
    float A0[TB][NU];
    float A1[TB][NU];
    float Ws[32][NU];
};

__global__ __launch_bounds__(256) void k5_out(const float* __restrict__ inp,
                                              const float* __restrict__ outW,
                                              const float* __restrict__ outb,
                                              float* __restrict__ out, int B){
    extern __shared__ char smraw[];
    SM5& S = *(SM5*)smraw;
    int t = threadIdx.x, rg = t>>5, cg = t&31;
    int b0 = blockIdx.x*TB;

    for(int i=t; i<TB*NU; i+=256){
        int r = i>>7, c = i&127;
        S.A0[r][c] = g_htilde[(size_t)(b0+r)*NU + c];
        S.A1[r][c] = inp[(size_t)(b0+r)*INC + NU + MS + c];
    }

    float acc[4][4];
    #pragma unroll
    for(int i=0;i<4;i++){ acc[i][0]=acc[i][1]=acc[i][2]=acc[i][3]=0.f; }
    gemm_rt(S.A0, outW,         S.Ws, rg, cg, acc);
    gemm_rt(S.A1, outW + NU*NU, S.Ws, rg, cg, acc);

    float s[4];
    #pragma unroll
    for(int i=0;i<4;i++){
        s[i]=0.f;
        #pragma unroll
        for(int j=0;j<4;j++) s[i] += sigmoidf(acc[i][j] + outb[cg*4+j]);
    }
    #pragma unroll
    for(int off=16; off; off>>=1){
        #pragma unroll
        for(int i=0;i<4;i++) s[i] += __shfl_xor_sync(0xffffffffu, s[i], off);
    }
    if(cg==0){
        #pragma unroll
        for(int i=0;i<4;i++){
            int b = b0 + rg*4 + i;
            float p  = g_preds[b];
            float ap = s[i] * (1.f/NU);
            out[(size_t)b*2]     = p;
            out[(size_t)b*2 + 1] = (ap - p) / (1.f - p);
        }
    }
}

// ---------------- launch ----------------
extern "C" void kernel_launch(void* const* d_in, const int* in_sizes, int n_in,
                              void* d_out, int out_size){
    const float* inp    = (const float*)d_in[0];
    const float* states = (const float*)d_in[1];
    const float* tw     = (const float*)d_in[2];
    const float* aw     = (const float*)d_in[3];
    const float* hw     = (const float*)d_in[4];
    const float* Wf     = (const float*)d_in[5];
    const float* bias   = (const float*)d_in[6];
    const float* g3W    = (const float*)d_in[7];
    const float* g3b    = (const float*)d_in[8];
    const float* outW   = (const float*)d_in[9];
    const float* outb   = (const float*)d_in[10];
    const float* tgW    = (const float*)d_in[11];
    const float* tgb    = (const float*)d_in[12];
    const float* agW    = (const float*)d_in[13];
    const float* agb    = (const float*)d_in[14];
    const float* hgW    = (const float*)d_in[15];
    const float* hgb    = (const float*)d_in[16];
    float* out = (float*)d_out;
    int B = in_sizes[0] / INC;

    cudaFuncSetAttribute(k2a,     cudaFuncAttributeMaxDynamicSharedMemorySize, (int)sizeof(SM2A));
    cudaFuncSetAttribute(k2b,     cudaFuncAttributeMaxDynamicSharedMemorySize, (int)sizeof(SM2B));
    cudaFuncSetAttribute(k4_main, cudaFuncAttributeMaxDynamicSharedMemorySize, SM4_TOTAL);
    cudaFuncSetAttribute(k5_out,  cudaFuncAttributeMaxDynamicSharedMemorySize, (int)sizeof(SM5));

    k0_wsum   <<<1, 128>>>(g3W);
    k0b_wsplit<<<64, 256>>>(g3W);
    k1_hpt    <<<B, 128>>>(inp, states);
    {
        dim3 g2a(B/TB, 5);
        k2a<<<g2a, 256, sizeof(SM2A)>>>(inp, outW, outb, tgW, tgb, agW, agb, hgW, hgb, g3W, g3b);
    }
    {
        dim3 g2b(B/TB, 4);
        k2b<<<g2b, 256, sizeof(SM2B)>>>(tw, aw, hw, Wf);
    }
    k3c      <<<(B*NU/4 + 255)/256, 256>>>(bias, B);
    k4_main  <<<B/2, 256, SM4_TOTAL>>>(inp, states, out, B);
    k5_out   <<<B/TB, 256, sizeof(SM5)>>>(inp, outW, outb, out, B);
}

// round 13
// speedup vs baseline: 1.1383x; 1.1383x over previous
#include <cuda_runtime.h>
#include <cuda_bf16.h>
#include <cstdint>

#define NU   128
#define MS   64
#define INC  323          // [0:128) interact | [128:192) corr | [192:320) topic | 320 t | 321 a | 322 h
#define BMAX 4096
#define TB   32

// ---------------- scratch (device globals; no allocation) ----------------
__device__ float g_hpt   [BMAX*NU];
__device__ float g_lg    [BMAX*NU];
__device__ float g_c     [BMAX*NU];
__device__ float g_preds [BMAX];
__device__ float g_htilde[BMAX*NU];
__device__ float g_ws    [3*NU];
__device__ float g_gain  [3*BMAX*NU];
__device__ float g_fdot  [12ULL*BMAX*NU];
// 22 weight tiles, each 128x128 bf16, transposed + swizzled, hi/lo split:
// 0,1: outW | 2,3: tgW | 4,5: agW | 6,7: hgW | 8: g3W[128:256] | 9: g3W[0:128] (k4)
// 10+y (y=0..11): fusion W (y%3 -> tw/aw/hw), rows r*129..r*129+127, r=y/3
__device__ __nv_bfloat16 g_wsphi[22*NU*NU];
__device__ __nv_bfloat16 g_wsplo[22*NU*NU];

__device__ __forceinline__ float sigmoidf(float x){ return 1.f/(1.f+__expf(-x)); }
__device__ __forceinline__ int swzA(int row, int cb){ return row*256 + (cb ^ ((row&7)<<4)); }
__device__ __forceinline__ uint32_t bfu(__nv_bfloat16 h){ return (uint32_t)__bfloat16_as_ushort(h); }

#define MMA16816(c, a, b0v, b1v) \
    asm volatile("mma.sync.aligned.m16n8k16.row.col.f32.bf16.bf16.f32 " \
        "{%0,%1,%2,%3}, {%4,%5,%6,%7}, {%8,%9}, {%0,%1,%2,%3};" \
        : "+f"((c)[0]), "+f"((c)[1]), "+f"((c)[2]), "+f"((c)[3]) \
        : "r"((a)[0]), "r"((a)[1]), "r"((a)[2]), "r"((a)[3]), "r"(b0v), "r"(b1v))

// ---------------- K0: colsums of gate3_W factor rows ----------------
__global__ void k0_wsum(const float* __restrict__ g3W){
    int n = threadIdx.x;
    #pragma unroll
    for(int g=0; g<3; g++){
        float s = 0.f;
        for(int u=0; u<50; u++) s += g3W[(256 + g*50 + u)*NU + n];
        g_ws[g*NU + n] = s;
    }
}

// ---------------- K0c: split ALL weight tiles -> bf16 hi/lo, transposed + swizzled ----------------
__global__ __launch_bounds__(256) void k0c(const float* __restrict__ outW,
    const float* __restrict__ tgW, const float* __restrict__ agW,
    const float* __restrict__ hgW, const float* __restrict__ g3W,
    const float* __restrict__ tw,  const float* __restrict__ aw,
    const float* __restrict__ hw){
    int tile = blockIdx.y;
    int id = blockIdx.x*256 + threadIdx.x;
    int n = id>>7, k = id&127;
    float v;
    if(tile < 2)      v = outW[(size_t)(k + tile*128)*NU + n];
    else if(tile < 4) v = tgW [(size_t)(k + (tile-2)*128)*NU + n];
    else if(tile < 6) v = agW [(size_t)(k + (tile-4)*128)*NU + n];
    else if(tile < 8) v = hgW [(size_t)(k + (tile-6)*128)*NU + n];
    else if(tile == 8) v = g3W[(size_t)(k + 128)*NU + n];
    else if(tile == 9) v = g3W[(size_t)k*NU + n];
    else {
        int y = tile - 10;
        const float* W = (y%3==0)? tw : (y%3==1)? aw : hw;
        v = W[((size_t)(y/3)*129 + k)*NU + n];
    }
    __nv_bfloat16 hi = __float2bfloat16(v);
    __nv_bfloat16 lo = __float2bfloat16(v - __bfloat162float(hi));
    int off = tile*32768 + swzA(n, 2*k);
    *(__nv_bfloat16*)((char*)g_wsphi + off) = hi;
    *(__nv_bfloat16*)((char*)g_wsplo + off) = lo;
}

// ---------------- K1: h_pre_tilde ----------------
__global__ __launch_bounds__(128) void k1_hpt(const float* __restrict__ inp,
                                              const float* __restrict__ states){
    int b = blockIdx.x, n = threadIdx.x;
    __shared__ float corr[MS];
    if(n < MS) corr[n] = inp[(size_t)b*INC + NU + n];
    __syncthreads();
    const float* hp = states + (size_t)b*MS*NU;
    float a0=0.f,a1=0.f,a2=0.f,a3=0.f;
    #pragma unroll
    for(int m=0; m<MS; m+=4){
        a0 = fmaf(corr[m+0], hp[(m+0)*NU + n], a0);
        a1 = fmaf(corr[m+1], hp[(m+1)*NU + n], a1);
        a2 = fmaf(corr[m+2], hp[(m+2)*NU + n], a2);
        a3 = fmaf(corr[m+3], hp[(m+3)*NU + n], a3);
    }
    g_hpt[b*NU + n] = (a0+a1)+(a2+a3);
}

// ================= shared helpers for mma kernels =================
// stage a [32][128] fp32 source into smem as swizzled bf16 hi (dst+0) / lo (dst+8192)
__device__ __forceinline__ void stage_tile(char* dst, const float* __restrict__ src,
                                           int rstride){
    int t = threadIdx.x;
    for(int idx=t; idx<32*64; idx+=256){
        int row = idx>>6, c0 = (idx&63)*2;
        const float* sr = src + (size_t)row*rstride;
        float x = sr[c0], y = sr[c0+1];
        __nv_bfloat16 hx = __float2bfloat16(x), hy = __float2bfloat16(y);
        uint32_t hv = bfu(hx) | (bfu(hy)<<16);
        uint32_t lv = bfu(__float2bfloat16(x - __bfloat162float(hx)))
                    | (bfu(__float2bfloat16(y - __bfloat162float(hy)))<<16);
        int off = swzA(row, c0*2);
        *(uint32_t*)(dst + off)        = hv;
        *(uint32_t*)(dst + 8192 + off) = lv;
    }
}

// one K=128 pass: acc[mt][nt][] += A[32,128] @ W^T[128,128] (3-term hi/lo)
// warp ng covers cols [ng*16, ng*16+16); A from smem, W from global (split tiles)
__device__ __forceinline__ void mma_pass(const char* smA, const char* Whi, const char* Wlo,
                                         int ng, int g, int tt, float acc[2][2][4]){
    #pragma unroll
    for(int kt=0; kt<8; kt++){
        int cb0 = kt*32 + tt*4, cb1 = cb0 + 16;
        uint32_t ah[2][4], al[2][4];
        #pragma unroll
        for(int mt=0; mt<2; mt++){
            int r0 = mt*16 + g, r1 = r0 + 8;
            ah[mt][0] = *(const uint32_t*)(smA + swzA(r0, cb0));
            ah[mt][1] = *(const uint32_t*)(smA + swzA(r1, cb0));
            ah[mt][2] = *(const uint32_t*)(smA + swzA(r0, cb1));
            ah[mt][3] = *(const uint32_t*)(smA + swzA(r1, cb1));
            al[mt][0] = *(const uint32_t*)(smA + 8192 + swzA(r0, cb0));
            al[mt][1] = *(const uint32_t*)(smA + 8192 + swzA(r1, cb0));
            al[mt][2] = *(const uint32_t*)(smA + 8192 + swzA(r0, cb1));
            al[mt][3] = *(const uint32_t*)(smA + 8192 + swzA(r1, cb1));
        }
        #pragma unroll
        for(int nt=0; nt<2; nt++){
            int brow = ng*16 + nt*8 + g;
            uint32_t bh0 = *(const uint32_t*)(Whi + swzA(brow, cb0));
            uint32_t bh1 = *(const uint32_t*)(Whi + swzA(brow, cb1));
            uint32_t bl0 = *(const uint32_t*)(Wlo + swzA(brow, cb0));
            uint32_t bl1 = *(const uint32_t*)(Wlo + swzA(brow, cb1));
            #pragma unroll
            for(int mt=0; mt<2; mt++){
                MMA16816(acc[mt][nt], ah[mt], bh0, bh1);
                MMA16816(acc[mt][nt], al[mt], bh0, bh1);
                MMA16816(acc[mt][nt], ah[mt], bl0, bl1);
            }
        }
    }
}

// ---------------- K2a mma: slot 0=preds, 1..3=gates, 4=c ----------------
__global__ __launch_bounds__(256) void k2a_mma(const float* __restrict__ inp,
    const float* __restrict__ outb, const float* __restrict__ tgb,
    const float* __restrict__ agb,  const float* __restrict__ hgb,
    const float* __restrict__ g3b){

    extern __shared__ char sm[];          // [tile0 16KB][tile1 16KB][red 1KB]
    int t = threadIdx.x;
    int slot = blockIdx.y;
    int b0 = blockIdx.x*TB;

    if(slot == 0){
        stage_tile(sm,         g_hpt + (size_t)b0*NU, NU);
        stage_tile(sm + 16384, inp + (size_t)b0*INC + NU + MS, INC);
    } else if(slot <= 3){
        stage_tile(sm,         g_hpt + (size_t)b0*NU, NU);
        stage_tile(sm + 16384, inp + (size_t)b0*INC, INC);
    } else {
        stage_tile(sm,         inp + (size_t)b0*INC, INC);
    }
    __syncthreads();

    int ng = t>>5, l = t&31, g = l>>2, tt = l&3;
    float acc[2][2][4];
    #pragma unroll
    for(int mt=0;mt<2;mt++) for(int nt=0;nt<2;nt++)
        { acc[mt][nt][0]=acc[mt][nt][1]=acc[mt][nt][2]=acc[mt][nt][3]=0.f; }

    if(slot < 4){
        int t0 = slot*2;
        mma_pass(sm,        (const char*)g_wsphi + t0*32768,     (const char*)g_wsplo + t0*32768,     ng, g, tt, acc);
        mma_pass(sm+16384,  (const char*)g_wsphi + (t0+1)*32768, (const char*)g_wsplo + (t0+1)*32768, ng, g, tt, acc);
    } else {
        mma_pass(sm, (const char*)g_wsphi + 8*32768, (const char*)g_wsplo + 8*32768, ng, g, tt, acc);
    }

    if(slot == 0){
        float* red = (float*)(sm + 32768);   // [32][8]
        #pragma unroll
        for(int mt=0;mt<2;mt++)
            #pragma unroll
            for(int i=0;i<2;i++){
                int row = mt*16 + g + i*8;
                float p = 0.f;
                #pragma unroll
                for(int nt=0;nt<2;nt++){
                    int c0 = ng*16 + nt*8 + tt*2;
                    p += sigmoidf(acc[mt][nt][2*i]   + outb[c0]);
                    p += sigmoidf(acc[mt][nt][2*i+1] + outb[c0+1]);
                }
                p += __shfl_xor_sync(0xffffffffu, p, 1);
                p += __shfl_xor_sync(0xffffffffu, p, 2);
                if(tt == 0) red[row*8 + ng] = p;
            }
        __syncthreads();
        if(t < 32){
            float s = 0.f;
            #pragma unroll
            for(int k=0;k<8;k++) s += red[t*8 + k];
            g_preds[b0 + t] = s * (1.f/NU);
        }
    } else if(slot <= 3){
        int gi = slot - 1;
        const float* bg = (gi==0)? tgb : (gi==1)? agb : hgb;
        float* dst = g_gain + (size_t)gi*BMAX*NU;
        #pragma unroll
        for(int mt=0;mt<2;mt++)
            #pragma unroll
            for(int i=0;i<2;i++){
                int row = mt*16 + g + i*8;
                int b = b0 + row;
                float f = inp[(size_t)b*INC + 320 + gi];
                float gain = 0.3f + 0.7f*sigmoidf(10.f*(f - 0.3f));
                #pragma unroll
                for(int nt=0;nt<2;nt++){
                    int c0 = ng*16 + nt*8 + tt*2;
                    float2 bv = *(const float2*)&bg[c0];
                    float2 o;
                    o.x = sigmoidf((acc[mt][nt][2*i]   + bv.x) * gain);
                    o.y = sigmoidf((acc[mt][nt][2*i+1] + bv.y) * gain);
                    *(float2*)&dst[(size_t)b*NU + c0] = o;
                }
            }
    } else {
        #pragma unroll
        for(int mt=0;mt<2;mt++)
            #pragma unroll
            for(int i=0;i<2;i++){
                int row = mt*16 + g + i*8;
                int b = b0 + row;
                float f0 = inp[(size_t)b*INC + 320];
                float f1 = inp[(size_t)b*INC + 321];
                float f2 = inp[(size_t)b*INC + 322];
                #pragma unroll
                for(int nt=0;nt<2;nt++){
                    int c0 = ng*16 + nt*8 + tt*2;
                    float2 w0 = *(const float2*)&g_ws[c0];
                    float2 w1 = *(const float2*)&g_ws[NU + c0];
                    float2 w2 = *(const float2*)&g_ws[2*NU + c0];
                    float2 bv = *(const float2*)&g3b[c0];
                    float2 o;
                    o.x = acc[mt][nt][2*i]   + f0*w0.x + f1*w1.x + f2*w2.x + bv.x;
                    o.y = acc[mt][nt][2*i+1] + f0*w0.y + f1*w1.y + f2*w2.y + bv.y;
                    *(float2*)&g_c[(size_t)b*NU + c0] = o;
                }
            }
    }
}

// ---------------- K2b mma: 12 fusion dot products ----------------
__global__ __launch_bounds__(256) void k2b_mma(const float* __restrict__ tw,
    const float* __restrict__ aw, const float* __restrict__ hw){
    extern __shared__ char sm[];
    int t = threadIdx.x;
    int y = blockIdx.y;                   // y = r*3 + g
    int b0 = blockIdx.x*TB;
    int r = y/3, gi = y%3;

    stage_tile(sm, g_gain + (size_t)gi*BMAX*NU + (size_t)b0*NU, NU);
    __syncthreads();

    int ng = t>>5, l = t&31, g = l>>2, tt = l&3;
    float acc[2][2][4];
    #pragma unroll
    for(int mt=0;mt<2;mt++) for(int nt=0;nt<2;nt++)
        { acc[mt][nt][0]=acc[mt][nt][1]=acc[mt][nt][2]=acc[mt][nt][3]=0.f; }

    int tile = 10 + y;
    mma_pass(sm, (const char*)g_wsphi + (size_t)tile*32768,
                 (const char*)g_wsplo + (size_t)tile*32768, ng, g, tt, acc);

    const float* W = (gi==0)? tw : (gi==1)? aw : hw;
    const float* pad = W + ((size_t)r*129 + 128)*NU;
    float* dst = g_fdot + (size_t)y*BMAX*NU;
    #pragma unroll
    for(int mt=0;mt<2;mt++)
        #pragma unroll
        for(int i=0;i<2;i++){
            int row = mt*16 + g + i*8;
            int b = b0 + row;
            #pragma unroll
            for(int nt=0;nt<2;nt++){
                int c0 = ng*16 + nt*8 + tt*2;
                float2 pv = *(const float2*)&pad[c0];
                float2 o;
                o.x = acc[mt][nt][2*i]   + pv.x;
                o.y = acc[mt][nt][2*i+1] + pv.y;
                *(float2*)&dst[(size_t)b*NU + c0] = o;
            }
        }
}

// ---------------- K3c: combine -> learning_gain (R9) ----------------
__global__ __launch_bounds__(256) void k3c(const float* __restrict__ Wf,
                                           const float* __restrict__ bias, int B){
    int idx = blockIdx.x*256 + threadIdx.x;
    size_t e = (size_t)idx*4;
    if(e >= (size_t)B*NU) return;
    int n = (int)(e & 127);
    float wfs[4] = {__ldg(Wf), __ldg(Wf+1), __ldg(Wf+2), __ldg(Wf+3)};
    float4 bs = *(const float4*)&bias[n];
    float4 acc = make_float4(0.f,0.f,0.f,0.f);
    #pragma unroll
    for(int r=0; r<4; r++){
        float4 p0 = *(const float4*)&g_fdot[(size_t)(r*3+0)*BMAX*NU + e];
        float4 p1 = *(const float4*)&g_fdot[(size_t)(r*3+1)*BMAX*NU + e];
        float4 p2 = *(const float4*)&g_fdot[(size_t)(r*3+2)*BMAX*NU + e];
        acc.x = fmaf(wfs[r], p0.x*p1.x*p2.x, acc.x);
        acc.y = fmaf(wfs[r], p0.y*p1.y*p2.y, acc.y);
        acc.z = fmaf(wfs[r], p0.z*p1.z*p2.z, acc.z);
        acc.w = fmaf(wfs[r], p0.w*p1.w*p2.w, acc.w);
    }
    float4 o;
    o.x = fmaxf(acc.x + bs.x, 0.f);
    o.y = fmaxf(acc.y + bs.y, 0.f);
    o.z = fmaxf(acc.z + bs.z, 0.f);
    o.w = fmaxf(acc.w + bs.w, 0.f);
    *(float4*)&g_lg[e] = o;
}

// ---------------- K4 (R9 v2): mma GEMM (A from global) + state update + h_tilde ----------------
#define SM4_WHI 0
#define SM4_WLO 32768
#define SM4_HTW 65536
#define SM4_AUX (65536 + 4096)
#define SM4_TOTAL (SM4_AUX + 2560)

__global__ __launch_bounds__(256, 2)
void k4_main(const float* __restrict__ inp, const float* __restrict__ states,
             float* __restrict__ out, int B){
    extern __shared__ char sm[];
    float* htw    = (float*)(sm + SM4_HTW);
    float* corr_s = (float*)(sm + SM4_AUX);
    float* c_s    = (float*)(sm + SM4_AUX + 512);
    float* lg_s   = (float*)(sm + SM4_AUX + 1536);

    int t = threadIdx.x, w = t>>5, l = t&31;
    int g = l>>2, tt = l&3;
    int bb = blockIdx.x;
    size_t row0 = (size_t)bb*128;

    {
        const uint4* shv = (const uint4*)((const char*)g_wsphi + 9*32768);
        const uint4* slv = (const uint4*)((const char*)g_wsplo + 9*32768);
        uint4* dh = (uint4*)(sm + SM4_WHI);
        uint4* dl = (uint4*)(sm + SM4_WLO);
        for(int i=t; i<2048; i+=256){ dh[i]=shv[i]; dl[i]=slv[i]; }
    }
    if(t < 128) corr_s[t] = inp[(size_t)(2*bb + (t>>6))*INC + NU + (t&63)];
    c_s[t]  = g_c [(size_t)2*bb*NU + t];
    lg_s[t] = g_lg[(size_t)2*bb*NU + t];

    int r0 = w*16;
    const float* a00 = states + (row0 + r0 + g    )*NU;
    const float* a01 = states + (row0 + r0 + g + 8)*NU;

    float acc[16][4];
    #pragma unroll
    for(int nt=0; nt<16; nt++){ acc[nt][0]=acc[nt][1]=acc[nt][2]=acc[nt][3]=0.f; }

    __syncthreads();

    float2 av0[4], av1[4];
    {
        int c0 = tt*2;
        av0[0] = *(const float2*)(a00 + c0);
        av0[1] = *(const float2*)(a01 + c0);
        av0[2] = *(const float2*)(a00 + c0 + 8);
        av0[3] = *(const float2*)(a01 + c0 + 8);
    }
    #pragma unroll
    for(int kt=0; kt<8; kt++){
        if(kt < 7){
            int c0 = (kt+1)*16 + tt*2;
            av1[0] = *(const float2*)(a00 + c0);
            av1[1] = *(const float2*)(a01 + c0);
            av1[2] = *(const float2*)(a00 + c0 + 8);
            av1[3] = *(const float2*)(a01 + c0 + 8);
        }
        uint32_t ah[4], al[4];
        #pragma unroll
        for(int i=0;i<4;i++){
            float x = av0[i].x, y = av0[i].y;
            __nv_bfloat16 hx = __float2bfloat16(x), hy = __float2bfloat16(y);
            ah[i] = bfu(hx) | (bfu(hy)<<16);
            al[i] = bfu(__float2bfloat16(x - __bfloat162float(hx)))
                  | (bfu(__float2bfloat16(y - __bfloat162float(hy)))<<16);
        }
        int cb0 = kt*32 + tt*4, cb1 = cb0 + 16;
        #pragma unroll
        for(int nt=0; nt<16; nt++){
            uint32_t bh0 = *(const uint32_t*)(sm + SM4_WHI + swzA(nt*8+g, cb0));
            uint32_t bh1 = *(const uint32_t*)(sm + SM4_WHI + swzA(nt*8+g, cb1));
            uint32_t bl0 = *(const uint32_t*)(sm + SM4_WLO + swzA(nt*8+g, cb0));
            uint32_t bl1 = *(const uint32_t*)(sm + SM4_WLO + swzA(nt*8+g, cb1));
            MMA16816(acc[nt], ah, bh0, bh1);
            MMA16816(acc[nt], al, bh0, bh1);
            MMA16816(acc[nt], ah, bl0, bl1);
        }
        #pragma unroll
        for(int i=0;i<4;i++) av0[i] = av1[i];
    }

    int m0 = r0 + g, m1 = r0 + g + 8;
    int boff = (m0 >> 6) * NU;
    float cr0 = corr_s[m0], cr1 = corr_s[m1];
    float* h0 = out + (size_t)2*B + (row0 + m0)*NU;
    float* h1 = out + (size_t)2*B + (row0 + m1)*NU;

    #pragma unroll
    for(int nt=0; nt<16; nt++){
        int n0 = nt*8 + tt*2;
        float2 a0v = *(const float2*)(a00 + n0);
        float2 a1v = *(const float2*)(a01 + n0);
        float2 cc  = *(const float2*)(c_s  + boff + n0);
        float2 ll  = *(const float2*)(lg_s + boff + n0);
        float2 o0, o1;
        o0.x = a0v.x * sigmoidf(acc[nt][0] + cc.x) + cr0*ll.x;
        o0.y = a0v.y * sigmoidf(acc[nt][1] + cc.y) + cr0*ll.y;
        o1.x = a1v.x * sigmoidf(acc[nt][2] + cc.x) + cr1*ll.x;
        o1.y = a1v.y * sigmoidf(acc[nt][3] + cc.y) + cr1*ll.y;
        *(float2*)(h0 + n0) = o0;
        *(float2*)(h1 + n0) = o1;
        float px = fmaf(cr0, o0.x, cr1*o1.x);
        float py = fmaf(cr0, o0.y, cr1*o1.y);
        px += __shfl_xor_sync(0xffffffffu, px, 4);
        py += __shfl_xor_sync(0xffffffffu, py, 4);
        px += __shfl_xor_sync(0xffffffffu, px, 8);
        py += __shfl_xor_sync(0xffffffffu, py, 8);
        px += __shfl_xor_sync(0xffffffffu, px, 16);
        py += __shfl_xor_sync(0xffffffffu, py, 16);
        if(g == 0){ htw[w*NU + n0] = px; htw[w*NU + n0 + 1] = py; }
    }
    __syncthreads();
    {
        int batch = t>>7, col = t&127;
        float s = htw[(batch*4+0)*NU + col] + htw[(batch*4+1)*NU + col]
                + htw[(batch*4+2)*NU + col] + htw[(batch*4+3)*NU + col];
        g_htilde[(size_t)(2*bb + batch)*NU + col] = s;
    }
}

// ================= register-tiled GEMM core (k5 only) =================
__device__ __forceinline__ void gemm_rt(const float (*A)[NU], const float* __restrict__ W,
                                        float (*Ws)[NU], int rg, int cg, float acc[4][4]){
    int t = threadIdx.x;
    float4 pre[4];
    {
        const float4* src = (const float4*)W;
        #pragma unroll
        for(int i=0;i<4;i++) pre[i] = src[t + i*256];
    }
    #pragma unroll 1
    for(int kt=0; kt<4; kt++){
        __syncthreads();
        {
            float4* dst = (float4*)Ws;
            #pragma unroll
            for(int i=0;i<4;i++) dst[t + i*256] = pre[i];
        }
        __syncthreads();
        if(kt < 3){
            const float4* src = (const float4*)(W + (kt+1)*32*NU);
            #pragma unroll
            for(int i=0;i<4;i++) pre[i] = src[t + i*256];
        }
        #pragma unroll
        for(int k=0; k<32; k+=4){
            float4 w0 = *(const float4*)&Ws[k+0][cg*4];
            float4 w1 = *(const float4*)&Ws[k+1][cg*4];
            float4 w2 = *(const float4*)&Ws[k+2][cg*4];
            float4 w3 = *(const float4*)&Ws[k+3][cg*4];
            #pragma unroll
            for(int i=0;i<4;i++){
                float4 a = *(const float4*)&A[rg*4+i][kt*32+k];
                acc[i][0]=fmaf(a.x,w0.x,fmaf(a.y,w1.x,fmaf(a.z,w2.x,fmaf(a.w,w3.x,acc[i][0]))));
                acc[i][1]=fmaf(a.x,w0.y,fmaf(a.y,w1.y,fmaf(a.z,w2.y,fmaf(a.w,w3.y,acc[i][1]))));
                acc[i][2]=fmaf(a.x,w0.z,fmaf(a.y,w1.z,fmaf(a.z,w2.z,fmaf(a.w,w3.z,acc[i][2]))));
                acc[i][3]=fmaf(a.x,w0.w,fmaf(a.y,w1.w,fmaf(a.z,w2.w,fmaf(a.w,w3.w,acc[i][3]))));
            }
        }
    }
}

// ---------------- K5: after_preds from g_htilde + result ----------------
struct SM5 {
    float A0[TB][NU];
    float A1[TB][NU];
    float Ws[32][NU];
};

__global__ __launch_bounds__(256) void k5_out(const float* __restrict__ inp,
                                              const float* __restrict__ outW,
                                              const float* __restrict__ outb,
                                              float* __restrict__ out, int B){
    extern __shared__ char smraw[];
    SM5& S = *(SM5*)smraw;
    int t = threadIdx.x, rg = t>>5, cg = t&31;
    int b0 = blockIdx.x*TB;

    for(int i=t; i<TB*NU; i+=256){
        int r = i>>7, c = i&127;
        S.A0[r][c] = g_htilde[(size_t)(b0+r)*NU + c];
        S.A1[r][c] = inp[(size_t)(b0+r)*INC + NU + MS + c];
    }

    float acc[4][4];
    #pragma unroll
    for(int i=0;i<4;i++){ acc[i][0]=acc[i][1]=acc[i][2]=acc[i][3]=0.f; }
    gemm_rt(S.A0, outW,         S.Ws, rg, cg, acc);
    gemm_rt(S.A1, outW + NU*NU, S.Ws, rg, cg, acc);

    float s[4];
    #pragma unroll
    for(int i=0;i<4;i++){
        s[i]=0.f;
        #pragma unroll
        for(int j=0;j<4;j++) s[i] += sigmoidf(acc[i][j] + outb[cg*4+j]);
    }
    #pragma unroll
    for(int off=16; off; off>>=1){
        #pragma unroll
        for(int i=0;i<4;i++) s[i] += __shfl_xor_sync(0xffffffffu, s[i], off);
    }
    if(cg==0){
        #pragma unroll
        for(int i=0;i<4;i++){
            int b = b0 + rg*4 + i;
            float p  = g_preds[b];
            float ap = s[i] * (1.f/NU);
            out[(size_t)b*2]     = p;
            out[(size_t)b*2 + 1] = (ap - p) / (1.f - p);
        }
    }
}

// ---------------- launch ----------------
extern "C" void kernel_launch(void* const* d_in, const int* in_sizes, int n_in,
                              void* d_out, int out_size){
    const float* inp    = (const float*)d_in[0];
    const float* states = (const float*)d_in[1];
    const float* tw     = (const float*)d_in[2];
    const float* aw     = (const float*)d_in[3];
    const float* hw     = (const float*)d_in[4];
    const float* Wf     = (const float*)d_in[5];
    const float* bias   = (const float*)d_in[6];
    const float* g3W    = (const float*)d_in[7];
    const float* g3b    = (const float*)d_in[8];
    const float* outW   = (const float*)d_in[9];
    const float* outb   = (const float*)d_in[10];
    const float* tgW    = (const float*)d_in[11];
    const float* tgb    = (const float*)d_in[12];
    const float* agW    = (const float*)d_in[13];
    const float* agb    = (const float*)d_in[14];
    const float* hgW    = (const float*)d_in[15];
    const float* hgb    = (const float*)d_in[16];
    float* out = (float*)d_out;
    int B = in_sizes[0] / INC;

    cudaFuncSetAttribute(k4_main, cudaFuncAttributeMaxDynamicSharedMemorySize, SM4_TOTAL);
    cudaFuncSetAttribute(k5_out,  cudaFuncAttributeMaxDynamicSharedMemorySize, (int)sizeof(SM5));

    k0_wsum <<<1, 128>>>(g3W);
    {
        dim3 g0c(64, 22);
        k0c<<<g0c, 256>>>(outW, tgW, agW, hgW, g3W, tw, aw, hw);
    }
    k1_hpt  <<<B, 128>>>(inp, states);
    {
        dim3 g2a(B/TB, 5);
        k2a_mma<<<g2a, 256, 33792>>>(inp, outb, tgb, agb, hgb, g3b);
    }
    {
        dim3 g2b(B/TB, 12);
        k2b_mma<<<g2b, 256, 16384>>>(tw, aw, hw);
    }
    k3c     <<<(B*NU/4 + 255)/256, 256>>>(Wf, bias, B);
    k4_main <<<B/2, 256, SM4_TOTAL>>>(inp, states, out, B);
    k5_out  <<<B/TB, 256, sizeof(SM5)>>>(inp, outW, outb, out, B);
}